// round 10
// baseline (speedup 1.0000x reference)
#include <cuda_runtime.h>
#include <cuda_fp16.h>
#include <math.h>
#include <cstdint>

#define BATCH  2
#define SEQ    2048
#define DMODEL 1024
#define NHEADS 16
#define HDIM   64
#define MROWS  4096
#define KDIM   1024
#define NDIM   1024
#define TS ((size_t)MROWS * KDIM)
#define WS ((size_t)NDIM * KDIM)

typedef __half fp16;

// ---------------------------------------------------------------------------
// Scratch (allocation-free, __device__ globals)
// ---------------------------------------------------------------------------
__device__ fp16 g_inh[3][TS];
__device__ fp16 g_wh[4][WS];
__device__ fp16 g_qh[TS];
__device__ fp16 g_kh[TS];
__device__ fp16 g_vth[TS];
__device__ fp16 g_ah[TS];

// ---------------------------------------------------------------------------
// Helpers
// ---------------------------------------------------------------------------
__device__ __forceinline__ uint32_t smem_u32(const void* p) {
    uint32_t a;
    asm("{ .reg .u64 t; cvta.to.shared.u64 t, %1; cvt.u32.u64 %0, t; }" : "=r"(a) : "l"(p));
    return a;
}
__device__ __forceinline__ void cp16(uint32_t dst, const void* src) {
    asm volatile("cp.async.cg.shared.global [%0], [%1], 16;" :: "r"(dst), "l"(src));
}
__device__ __forceinline__ void cp_commit() { asm volatile("cp.async.commit_group;"); }
template<int N> __device__ __forceinline__ void cp_wait() {
    asm volatile("cp.async.wait_group %0;" :: "n"(N));
}
__device__ __forceinline__ uint32_t pack2_h(fp16 a, fp16 b) {
    return (uint32_t)__half_as_ushort(a) | ((uint32_t)__half_as_ushort(b) << 16);
}
__device__ __forceinline__ uint32_t cvtpack_h(float lo, float hi) {
    uint32_t r;
    asm("cvt.rn.f16x2.f32 %0, %1, %2;" : "=r"(r) : "f"(hi), "f"(lo));
    return r;
}
__device__ __forceinline__ float ex2f(float x) {
    float r;
    asm("ex2.approx.f32 %0, %1;" : "=f"(r) : "f"(x));
    return r;
}
__device__ __forceinline__ void mma_f16(float c[4], const uint32_t a[4],
                                        uint32_t b0, uint32_t b1) {
    asm volatile(
        "mma.sync.aligned.m16n8k16.row.col.f32.f16.f16.f32 "
        "{%0,%1,%2,%3}, {%4,%5,%6,%7}, {%8,%9}, {%0,%1,%2,%3};"
        : "+f"(c[0]), "+f"(c[1]), "+f"(c[2]), "+f"(c[3])
        : "r"(a[0]), "r"(a[1]), "r"(a[2]), "r"(a[3]), "r"(b0), "r"(b1));
}
__device__ __forceinline__ void ldsm4(uint32_t r[4], uint32_t addr) {
    asm volatile("ldmatrix.sync.aligned.m8n8.x4.shared.b16 {%0,%1,%2,%3}, [%4];"
                 : "=r"(r[0]), "=r"(r[1]), "=r"(r[2]), "=r"(r[3]) : "r"(addr));
}

// ---------------------------------------------------------------------------
// Pre-pass 1: convert 3 activation tensors fp32 -> fp16 (one launch)
// ---------------------------------------------------------------------------
__global__ __launch_bounds__(256)
void cvt_in(const float* __restrict__ q, const float* __restrict__ k,
            const float* __restrict__ v, fp16* __restrict__ outh)
{
    const float* in = (blockIdx.z == 0) ? q : (blockIdx.z == 1) ? k : v;
    size_t i = ((size_t)blockIdx.x * 256 + threadIdx.x) * 4;
    float4 x = *(const float4*)(in + i);
    *(uint2*)(outh + blockIdx.z * TS + i) =
        make_uint2(cvtpack_h(x.x, x.y), cvtpack_h(x.z, x.w));
}

// ---------------------------------------------------------------------------
// Pre-pass 2: transpose 4 weights -> fp16; Wq folds 0.125 * log2(e)
// ---------------------------------------------------------------------------
__global__ __launch_bounds__(256)
void tsplit_w(const float* __restrict__ Wq, const float* __restrict__ Wk,
              const float* __restrict__ Wv, const float* __restrict__ Wo,
              fp16* __restrict__ Wout)
{
    __shared__ float t[32][33];
    const int z = blockIdx.z;
    const float* W = (z == 0) ? Wq : (z == 1) ? Wk : (z == 2) ? Wv : Wo;
    const float scale = (z == 0) ? 0.18033688f : 1.0f;
    fp16* Wh = Wout + (size_t)z * WS;

    int x  = blockIdx.x * 32 + threadIdx.x;
    int y0 = blockIdx.y * 32;
#pragma unroll
    for (int i = 0; i < 32; i += 8)
        t[threadIdx.y + i][threadIdx.x] = W[(size_t)(y0 + threadIdx.y + i) * KDIM + x] * scale;
    __syncthreads();
    int xo = y0 + threadIdx.x;
    int yo = blockIdx.x * 32;
#pragma unroll
    for (int i = 0; i < 32; i += 8)
        Wh[(size_t)(yo + threadIdx.y + i) * KDIM + xo] =
            __float2half_rn(t[threadIdx.x][threadIdx.y + i]);
}

// ---------------------------------------------------------------------------
// GEMM mainloop, single-fp16. 128x128 tile, BK=32, 8 warps, 3 CTAs/SM target.
// ---------------------------------------------------------------------------
#define GSTR 40
#define GTEN 10240
#define GSTAGE (2 * GTEN)
#define GEMM_SMEM (2 * GSTAGE)

struct GemmCtx {
    int tid, wid, lane, gam, sig, wm, wn, row0, col0;
    uint32_t sb, offA, offB;
};

__device__ __forceinline__ void gemm_main(
    const fp16* __restrict__ Ah, const fp16* __restrict__ Bh,
    const GemmCtx& cx, float acc[2][8][4])
{
    auto issue = [&](int stage, int kc) {
        const uint32_t s0 = cx.sb + stage * GSTAGE;
        const int k0 = kc * 32;
#pragma unroll
        for (int i = 0; i < 2; i++) {
            int c = cx.tid + 256 * i;
            int r = c >> 2, ch = c & 3;
            uint32_t dst = (uint32_t)(r * 80 + ch * 16);
            cp16(s0 + dst,        Ah + (size_t)(cx.row0 + r) * KDIM + k0 + ch * 8);
            cp16(s0 + GTEN + dst, Bh + (size_t)(cx.col0 + r) * KDIM + k0 + ch * 8);
        }
        cp_commit();
    };

#pragma unroll
    for (int a = 0; a < 2; a++)
#pragma unroll
        for (int b = 0; b < 8; b++)
#pragma unroll
            for (int cq = 0; cq < 4; cq++) acc[a][b][cq] = 0.f;

    issue(0, 0);
    issue(1, 1);

    for (int kc = 0; kc < 32; kc++) {
        if (kc + 1 < 32) cp_wait<1>(); else cp_wait<0>();
        __syncthreads();
        const uint32_t s0 = cx.sb + (kc & 1) * GSTAGE;
        const uint32_t aah = s0 + cx.offA;
        const uint32_t bah = s0 + GTEN + cx.offB;

#pragma unroll
        for (int kk = 0; kk < 2; kk++) {
            uint32_t ah[2][4];
            ldsm4(ah[0], aah + kk * 32);
            ldsm4(ah[1], aah + 1280 + kk * 32);
#pragma unroll
            for (int gp = 0; gp < 2; gp++) {
                uint32_t b0[4], b1[4];
                ldsm4(b0, bah + (2 * gp)     * 1280 + kk * 32);
                ldsm4(b1, bah + (2 * gp + 1) * 1280 + kk * 32);
                mma_f16(acc[0][4 * gp + 0], ah[0], b0[0], b0[1]);
                mma_f16(acc[1][4 * gp + 0], ah[1], b0[0], b0[1]);
                mma_f16(acc[0][4 * gp + 1], ah[0], b0[2], b0[3]);
                mma_f16(acc[1][4 * gp + 1], ah[1], b0[2], b0[3]);
                mma_f16(acc[0][4 * gp + 2], ah[0], b1[0], b1[1]);
                mma_f16(acc[1][4 * gp + 2], ah[1], b1[0], b1[1]);
                mma_f16(acc[0][4 * gp + 3], ah[0], b1[2], b1[3]);
                mma_f16(acc[1][4 * gp + 3], ah[1], b1[2], b1[3]);
            }
        }
        __syncthreads();
        if (kc + 2 < 32) issue(kc & 1, kc + 2);
    }
}

__device__ __forceinline__ GemmCtx make_ctx(uint32_t sb) {
    GemmCtx cx;
    cx.tid = threadIdx.x; cx.wid = cx.tid >> 5; cx.lane = cx.tid & 31;
    cx.gam = cx.lane >> 2; cx.sig = cx.lane & 3;
    const int matid = cx.lane >> 3, mrow = cx.lane & 7;
    cx.wm = (cx.wid & 3) * 32; cx.wn = (cx.wid >> 2) * 64;
    cx.row0 = blockIdx.y * 128; cx.col0 = blockIdx.x * 128;
    cx.sb = sb;
    cx.offA = (uint32_t)((cx.wm + (matid & 1) * 8 + mrow) * 80 + (matid >> 1) * 16);
    cx.offB = (uint32_t)((cx.wn + (matid >> 1) * 8 + mrow) * 80 + (matid & 1) * 16);
    return cx;
}

// ---------------------------------------------------------------------------
// Fused Q/K/V projection GEMM. z=0: Q; z=1: K; z=2: V -> transposed.
// ---------------------------------------------------------------------------
__global__ __launch_bounds__(256, 3)
void gemm_qkv(const fp16* __restrict__ inh, const fp16* __restrict__ wh,
              fp16* __restrict__ qh, fp16* __restrict__ kh, fp16* __restrict__ vth)
{
    extern __shared__ char smem[];
    const int z = blockIdx.z;
    GemmCtx cx = make_ctx(smem_u32(smem));
    float acc[2][8][4];
    gemm_main(inh + (size_t)z * TS, wh + (size_t)z * WS, cx, acc);

    if (z < 2) {
        fp16* dst = (z == 0) ? qh : kh;
#pragma unroll
        for (int mt = 0; mt < 2; mt++)
#pragma unroll
            for (int nt = 0; nt < 8; nt++) {
                int r0 = cx.row0 + cx.wm + mt * 16 + cx.gam;
                int col = cx.col0 + cx.wn + nt * 8 + 2 * cx.sig;
                *(uint32_t*)(dst + (size_t)r0 * NDIM + col) =
                    cvtpack_h(acc[mt][nt][0], acc[mt][nt][1]);
                *(uint32_t*)(dst + (size_t)(r0 + 8) * NDIM + col) =
                    cvtpack_h(acc[mt][nt][2], acc[mt][nt][3]);
            }
    } else {
        fp16* tb = (fp16*)smem;   // [128][130]
        __syncthreads();
#pragma unroll
        for (int mt = 0; mt < 2; mt++)
#pragma unroll
            for (int nt = 0; nt < 8; nt++)
#pragma unroll
                for (int rr = 0; rr < 2; rr++) {
                    int lr = cx.wm + mt * 16 + cx.gam + rr * 8;
                    int lc = cx.wn + nt * 8 + 2 * cx.sig;
                    *(uint32_t*)(tb + lr * 130 + lc) =
                        cvtpack_h(acc[mt][nt][2 * rr], acc[mt][nt][2 * rr + 1]);
                }
        __syncthreads();
#pragma unroll 4
        for (int it = 0; it < 32; it++) {
            int c = (cx.tid >> 6) + it * 4;
            int r = (cx.tid & 63) * 2;
            uint32_t p = pack2_h(tb[r * 130 + c], tb[(r + 1) * 130 + c]);
            *(uint32_t*)(vth + (size_t)(cx.col0 + c) * MROWS + cx.row0 + r) = p;
        }
    }
}

// ---------------------------------------------------------------------------
// Output projection GEMM -> fp32
// ---------------------------------------------------------------------------
__global__ __launch_bounds__(256, 3)
void gemm_out(const fp16* __restrict__ Ah, const fp16* __restrict__ Bh,
              float* __restrict__ Cf)
{
    extern __shared__ char smem[];
    GemmCtx cx = make_ctx(smem_u32(smem));
    float acc[2][8][4];
    gemm_main(Ah, Bh, cx, acc);
#pragma unroll
    for (int mt = 0; mt < 2; mt++)
#pragma unroll
        for (int nt = 0; nt < 8; nt++) {
            int r0 = cx.row0 + cx.wm + mt * 16 + cx.gam;
            int col = cx.col0 + cx.wn + nt * 8 + 2 * cx.sig;
            *(float2*)(Cf + (size_t)r0 * NDIM + col) =
                make_float2(acc[mt][nt][0], acc[mt][nt][1]);
            *(float2*)(Cf + (size_t)(r0 + 8) * NDIM + col) =
                make_float2(acc[mt][nt][2], acc[mt][nt][3]);
        }
}

// ---------------------------------------------------------------------------
// Flash attention, half-split chunks for low register pressure (3 CTAs/SM).
// Unshifted softmax P = 2^s (s pre-scaled by log2e via Wq); row sums via
// all-ones MMA. 3-stage cp.async KV pipeline; Q fragments register-resident.
// Each chunk processed as two independent 32-T-column halves: only s[4][4]
// live at once; exp of one warp's half overlaps MMAs of other warps.
// ---------------------------------------------------------------------------
#define QTEN 18432
#define ATEN 9216
#define ASTAGE (2 * ATEN)
#define ASTAGES 3
#define ATT_SMEM (QTEN + ASTAGES * ASTAGE)   /* 73728; x3 CTAs = 221184 */

__global__ __launch_bounds__(256, 3)
void attn_h(const fp16* __restrict__ Qh, const fp16* __restrict__ Kh,
            const fp16* __restrict__ VTh, fp16* __restrict__ Oh)
{
    extern __shared__ char smem[];
    const uint32_t sb = smem_u32(smem);
    const int tid = threadIdx.x, wid = tid >> 5, lane = tid & 31;
    const int gam = lane >> 2, sig = lane & 3;
    const int matid = lane >> 3, mrow = lane & 7;
    const int b = blockIdx.y >> 4, n = blockIdx.y & 15;
    const int f0 = blockIdx.x * 128;
    const size_t qbase = ((size_t)b * SEQ + f0) * DMODEL + n * HDIM;

    const uint32_t offQ = (uint32_t)((wid * 16 + (matid & 1) * 8 + mrow) * 144 + (matid >> 1) * 16);
    const uint32_t offB = (uint32_t)(((matid >> 1) * 8 + mrow) * 144 + (matid & 1) * 16);
    const uint32_t ONES = 0x3C003C00u;   // fp16x2 (1.0, 1.0)

    // per-thread cp.async source pointers, advanced per issued chunk
    const int r1 = tid >> 3, ch1 = tid & 7;           // rows 0..31
    const int r2 = (tid + 256) >> 3, ch2 = tid & 7;   // rows 32..63
    const fp16* pk1 = Kh + ((size_t)b * SEQ + r1) * DMODEL + n * HDIM + ch1 * 8;
    const fp16* pk2 = Kh + ((size_t)b * SEQ + r2) * DMODEL + n * HDIM + ch2 * 8;
    const fp16* pv1 = VTh + ((size_t)(n * HDIM + r1)) * MROWS + (size_t)b * SEQ + ch1 * 8;
    const fp16* pv2 = VTh + ((size_t)(n * HDIM + r2)) * MROWS + (size_t)b * SEQ + ch2 * 8;
    const uint32_t d1 = (uint32_t)(r1 * 144 + ch1 * 16);
    const uint32_t d2 = (uint32_t)(r2 * 144 + ch2 * 16);

    auto issue_kv = [&](int stage) {
        const uint32_t s0 = sb + QTEN + stage * ASTAGE;
        cp16(s0 + d1,        pk1);
        cp16(s0 + d2,        pk2);
        cp16(s0 + ATEN + d1, pv1);
        cp16(s0 + ATEN + d2, pv2);
        cp_commit();
        pk1 += 64 * DMODEL; pk2 += 64 * DMODEL;
        pv1 += 64;          pv2 += 64;
    };

    // Q tile (joins stage-0 commit group)
#pragma unroll
    for (int i = 0; i < 4; i++) {
        int c = tid + 256 * i;
        int r = c >> 3, ch = c & 7;
        cp16(sb + (uint32_t)(r * 144 + ch * 16), Qh + qbase + (size_t)r * DMODEL + ch * 8);
    }
    issue_kv(0);
    issue_kv(1);
    issue_kv(2);

    float o[8][4], lacc[4];
#pragma unroll
    for (int nt = 0; nt < 8; nt++)
#pragma unroll
        for (int q = 0; q < 4; q++) o[nt][q] = 0.f;
#pragma unroll
    for (int q = 0; q < 4; q++) lacc[q] = 0.f;

    uint32_t qf[4][4];
    int stage = 0;

    for (int c = 0; c < 32; c++) {
        if (c < 30) cp_wait<2>(); else if (c == 30) cp_wait<1>(); else cp_wait<0>();
        __syncthreads();
        if (c == 0) {
#pragma unroll
            for (int kk = 0; kk < 4; kk++) ldsm4(qf[kk], sb + offQ + kk * 32);
        }
        const uint32_t s0 = sb + QTEN + stage * ASTAGE;
        const uint32_t kah = s0 + offB, vah = s0 + ATEN + offB;

#pragma unroll
        for (int hf = 0; hf < 2; hf++) {
            // ---- S half = Q @ K^T, T cols 32*hf .. 32*hf+31 ----
            float s[4][4];
#pragma unroll
            for (int j = 0; j < 4; j++)
#pragma unroll
                for (int q = 0; q < 4; q++) s[j][q] = 0.f;

#pragma unroll
            for (int kk = 0; kk < 4; kk++) {
                uint32_t b0[4], b1[4];
                ldsm4(b0, kah + (2 * hf)     * 2304 + kk * 32);
                ldsm4(b1, kah + (2 * hf + 1) * 2304 + kk * 32);
                mma_f16(s[0], qf[kk], b0[0], b0[1]);
                mma_f16(s[1], qf[kk], b0[2], b0[3]);
                mma_f16(s[2], qf[kk], b1[0], b1[1]);
                mma_f16(s[3], qf[kk], b1[2], b1[3]);
            }

            // ---- P = 2^s ----
#pragma unroll
            for (int j = 0; j < 4; j++) {
                s[j][0] = ex2f(s[j][0]);
                s[j][1] = ex2f(s[j][1]);
                s[j][2] = ex2f(s[j][2]);
                s[j][3] = ex2f(s[j][3]);
            }

            // ---- O += P @ V; row sums via all-ones MMA ----
#pragma unroll
            for (int j = 0; j < 2; j++) {
                const int k2 = 2 * hf + j;
                uint32_t ph[4];
                ph[0] = cvtpack_h(s[2 * j][0],     s[2 * j][1]);
                ph[1] = cvtpack_h(s[2 * j][2],     s[2 * j][3]);
                ph[2] = cvtpack_h(s[2 * j + 1][0], s[2 * j + 1][1]);
                ph[3] = cvtpack_h(s[2 * j + 1][2], s[2 * j + 1][3]);
#pragma unroll
                for (int gp = 0; gp < 2; gp++) {
                    uint32_t b0[4], b1[4];
                    ldsm4(b0, vah + (2 * gp)     * 2304 + k2 * 32);
                    ldsm4(b1, vah + (2 * gp + 1) * 2304 + k2 * 32);
                    mma_f16(o[4 * gp + 0], ph, b0[0], b0[1]);
                    mma_f16(o[4 * gp + 1], ph, b0[2], b0[3]);
                    mma_f16(o[4 * gp + 2], ph, b1[0], b1[1]);
                    mma_f16(o[4 * gp + 3], ph, b1[2], b1[3]);
                }
                mma_f16(lacc, ph, ONES, ONES);
            }
        }
        __syncthreads();
        if (c + 3 < 32) issue_kv(stage);
        stage = (stage == 2) ? 0 : stage + 1;
    }

    // ---- normalize, store ----
    const float inv0 = 1.f / lacc[0], inv1 = 1.f / lacc[2];
    const size_t ro0 = ((size_t)b * SEQ + f0 + wid * 16 + gam) * DMODEL + n * HDIM;
    const size_t ro1 = ro0 + 8 * DMODEL;
#pragma unroll
    for (int nt = 0; nt < 8; nt++) {
        const int col = nt * 8 + 2 * sig;
        *(uint32_t*)(Oh + ro0 + col) = cvtpack_h(o[nt][0] * inv0, o[nt][1] * inv0);
        *(uint32_t*)(Oh + ro1 + col) = cvtpack_h(o[nt][2] * inv1, o[nt][3] * inv1);
    }
}

// ---------------------------------------------------------------------------
// Launch: cvt(0), tsplit(1), gemm_qkv(2), attn(3), gemm_out(4)
// ---------------------------------------------------------------------------
extern "C" void kernel_launch(void* const* d_in, const int* in_sizes, int n_in,
                              void* d_out, int out_size)
{
    (void)in_sizes; (void)n_in; (void)out_size;
    const float* qin = (const float*)d_in[0];
    const float* kin = (const float*)d_in[1];
    const float* vin = (const float*)d_in[2];
    const float* Wq  = (const float*)d_in[3];
    const float* Wk  = (const float*)d_in[4];
    const float* Wv  = (const float*)d_in[5];
    const float* Wo  = (const float*)d_in[6];
    float* out = (float*)d_out;

    fp16 *inh, *wh, *qh, *kh, *vth, *ah;
    cudaGetSymbolAddress((void**)&inh, g_inh);
    cudaGetSymbolAddress((void**)&wh,  g_wh);
    cudaGetSymbolAddress((void**)&qh,  g_qh);
    cudaGetSymbolAddress((void**)&kh,  g_kh);
    cudaGetSymbolAddress((void**)&vth, g_vth);
    cudaGetSymbolAddress((void**)&ah,  g_ah);

    cudaFuncSetAttribute(gemm_qkv, cudaFuncAttributeMaxDynamicSharedMemorySize, GEMM_SMEM);
    cudaFuncSetAttribute(gemm_out, cudaFuncAttributeMaxDynamicSharedMemorySize, GEMM_SMEM);
    cudaFuncSetAttribute(attn_h,   cudaFuncAttributeMaxDynamicSharedMemorySize, ATT_SMEM);

    cvt_in<<<dim3((unsigned)(TS / 1024), 1, 3), 256>>>(qin, kin, vin, inh);
    tsplit_w<<<dim3(32, 32, 4), dim3(32, 8)>>>(Wq, Wk, Wv, Wo, wh);

    gemm_qkv<<<dim3(NDIM / 128, MROWS / 128, 3), 256, GEMM_SMEM>>>(
        inh, wh, qh, kh, vth);

    attn_h<<<dim3(SEQ / 128, BATCH * NHEADS), 256, ATT_SMEM>>>(
        qh, kh, vth, ah);

    gemm_out<<<dim3(NDIM / 128, MROWS / 128), 256, GEMM_SMEM>>>(
        ah, wh + 3 * WS, out);
}

// round 11
// speedup vs baseline: 1.3082x; 1.3082x over previous
#include <cuda_runtime.h>
#include <cuda_fp16.h>
#include <math.h>
#include <cstdint>

#define BATCH  2
#define SEQ    2048
#define DMODEL 1024
#define NHEADS 16
#define HDIM   64
#define MROWS  4096
#define KDIM   1024
#define NDIM   1024
#define TS ((size_t)MROWS * KDIM)
#define WS ((size_t)NDIM * KDIM)

typedef __half fp16;

// ---------------------------------------------------------------------------
// Scratch (allocation-free, __device__ globals)
// ---------------------------------------------------------------------------
__device__ fp16 g_inh[3][TS];
__device__ fp16 g_wh[4][WS];
__device__ fp16 g_qh[TS];
__device__ fp16 g_kh[TS];
__device__ fp16 g_vth[TS];
__device__ fp16 g_ah[TS];

// ---------------------------------------------------------------------------
// Helpers
// ---------------------------------------------------------------------------
__device__ __forceinline__ uint32_t smem_u32(const void* p) {
    uint32_t a;
    asm("{ .reg .u64 t; cvta.to.shared.u64 t, %1; cvt.u32.u64 %0, t; }" : "=r"(a) : "l"(p));
    return a;
}
__device__ __forceinline__ void cp16(uint32_t dst, const void* src) {
    asm volatile("cp.async.cg.shared.global [%0], [%1], 16;" :: "r"(dst), "l"(src));
}
__device__ __forceinline__ void cp_commit() { asm volatile("cp.async.commit_group;"); }
template<int N> __device__ __forceinline__ void cp_wait() {
    asm volatile("cp.async.wait_group %0;" :: "n"(N));
}
__device__ __forceinline__ uint32_t pack2_h(fp16 a, fp16 b) {
    return (uint32_t)__half_as_ushort(a) | ((uint32_t)__half_as_ushort(b) << 16);
}
__device__ __forceinline__ uint32_t cvtpack_h(float lo, float hi) {
    uint32_t r;
    asm("cvt.rn.f16x2.f32 %0, %1, %2;" : "=r"(r) : "f"(hi), "f"(lo));
    return r;
}
__device__ __forceinline__ float ex2f(float x) {
    float r;
    asm("ex2.approx.f32 %0, %1;" : "=f"(r) : "f"(x));
    return r;
}
__device__ __forceinline__ void mma_f16(float c[4], const uint32_t a[4],
                                        uint32_t b0, uint32_t b1) {
    asm volatile(
        "mma.sync.aligned.m16n8k16.row.col.f32.f16.f16.f32 "
        "{%0,%1,%2,%3}, {%4,%5,%6,%7}, {%8,%9}, {%0,%1,%2,%3};"
        : "+f"(c[0]), "+f"(c[1]), "+f"(c[2]), "+f"(c[3])
        : "r"(a[0]), "r"(a[1]), "r"(a[2]), "r"(a[3]), "r"(b0), "r"(b1));
}
__device__ __forceinline__ void ldsm4(uint32_t r[4], uint32_t addr) {
    asm volatile("ldmatrix.sync.aligned.m8n8.x4.shared.b16 {%0,%1,%2,%3}, [%4];"
                 : "=r"(r[0]), "=r"(r[1]), "=r"(r[2]), "=r"(r[3]) : "r"(addr));
}

// ---------------------------------------------------------------------------
// Pre-pass 1: convert 3 activation tensors fp32 -> fp16 (one launch)
// ---------------------------------------------------------------------------
__global__ __launch_bounds__(256)
void cvt_in(const float* __restrict__ q, const float* __restrict__ k,
            const float* __restrict__ v, fp16* __restrict__ outh)
{
    const float* in = (blockIdx.z == 0) ? q : (blockIdx.z == 1) ? k : v;
    size_t i = ((size_t)blockIdx.x * 256 + threadIdx.x) * 4;
    float4 x = *(const float4*)(in + i);
    *(uint2*)(outh + blockIdx.z * TS + i) =
        make_uint2(cvtpack_h(x.x, x.y), cvtpack_h(x.z, x.w));
}

// ---------------------------------------------------------------------------
// Pre-pass 2: transpose 4 weights -> fp16; Wq folds 0.125 * log2(e)
// ---------------------------------------------------------------------------
__global__ __launch_bounds__(256)
void tsplit_w(const float* __restrict__ Wq, const float* __restrict__ Wk,
              const float* __restrict__ Wv, const float* __restrict__ Wo,
              fp16* __restrict__ Wout)
{
    __shared__ float t[32][33];
    const int z = blockIdx.z;
    const float* W = (z == 0) ? Wq : (z == 1) ? Wk : (z == 2) ? Wv : Wo;
    const float scale = (z == 0) ? 0.18033688f : 1.0f;
    fp16* Wh = Wout + (size_t)z * WS;

    int x  = blockIdx.x * 32 + threadIdx.x;
    int y0 = blockIdx.y * 32;
#pragma unroll
    for (int i = 0; i < 32; i += 8)
        t[threadIdx.y + i][threadIdx.x] = W[(size_t)(y0 + threadIdx.y + i) * KDIM + x] * scale;
    __syncthreads();
    int xo = y0 + threadIdx.x;
    int yo = blockIdx.x * 32;
#pragma unroll
    for (int i = 0; i < 32; i += 8)
        Wh[(size_t)(yo + threadIdx.y + i) * KDIM + xo] =
            __float2half_rn(t[threadIdx.x][threadIdx.y + i]);
}

// ---------------------------------------------------------------------------
// GEMM mainloop, single-fp16. 128x128 tile, BK=64 (144B-stride rows, same
// proven layout as attention tiles), 8 warps, double-buffered. Half the
// barrier count of the BK=32 version; accumulation order over k unchanged.
// ---------------------------------------------------------------------------
#define GTEN 18432                  /* one tensor tile: 128 rows * 144 B */
#define GSTAGE (2 * GTEN)
#define GEMM_SMEM (2 * GSTAGE)      /* 73728 */

struct GemmCtx {
    int tid, wid, lane, gam, sig, wm, wn, row0, col0;
    uint32_t sb, offA, offB;
};

__device__ __forceinline__ void gemm_main(
    const fp16* __restrict__ Ah, const fp16* __restrict__ Bh,
    const GemmCtx& cx, float acc[2][8][4])
{
    auto issue = [&](int stage, int kc) {
        const uint32_t s0 = cx.sb + stage * GSTAGE;
        const int k0 = kc * 64;
#pragma unroll
        for (int i = 0; i < 4; i++) {
            int c = cx.tid + 256 * i;
            int r = c >> 3, ch = c & 7;
            uint32_t dst = (uint32_t)(r * 144 + ch * 16);
            cp16(s0 + dst,        Ah + (size_t)(cx.row0 + r) * KDIM + k0 + ch * 8);
            cp16(s0 + GTEN + dst, Bh + (size_t)(cx.col0 + r) * KDIM + k0 + ch * 8);
        }
        cp_commit();
    };

#pragma unroll
    for (int a = 0; a < 2; a++)
#pragma unroll
        for (int b = 0; b < 8; b++)
#pragma unroll
            for (int cq = 0; cq < 4; cq++) acc[a][b][cq] = 0.f;

    issue(0, 0);
    issue(1, 1);

    for (int kc = 0; kc < 16; kc++) {
        if (kc + 1 < 16) cp_wait<1>(); else cp_wait<0>();
        __syncthreads();
        const uint32_t s0 = cx.sb + (kc & 1) * GSTAGE;
        const uint32_t aah = s0 + cx.offA;
        const uint32_t bah = s0 + GTEN + cx.offB;

#pragma unroll
        for (int kk = 0; kk < 4; kk++) {
            uint32_t ah[2][4];
            ldsm4(ah[0], aah + kk * 32);
            ldsm4(ah[1], aah + 2304 + kk * 32);
#pragma unroll
            for (int gp = 0; gp < 2; gp++) {
                uint32_t b0[4], b1[4];
                ldsm4(b0, bah + (2 * gp)     * 2304 + kk * 32);
                ldsm4(b1, bah + (2 * gp + 1) * 2304 + kk * 32);
                mma_f16(acc[0][4 * gp + 0], ah[0], b0[0], b0[1]);
                mma_f16(acc[1][4 * gp + 0], ah[1], b0[0], b0[1]);
                mma_f16(acc[0][4 * gp + 1], ah[0], b0[2], b0[3]);
                mma_f16(acc[1][4 * gp + 1], ah[1], b0[2], b0[3]);
                mma_f16(acc[0][4 * gp + 2], ah[0], b1[0], b1[1]);
                mma_f16(acc[1][4 * gp + 2], ah[1], b1[0], b1[1]);
                mma_f16(acc[0][4 * gp + 3], ah[0], b1[2], b1[3]);
                mma_f16(acc[1][4 * gp + 3], ah[1], b1[2], b1[3]);
            }
        }
        __syncthreads();
        if (kc + 2 < 16) issue(kc & 1, kc + 2);
    }
}

__device__ __forceinline__ GemmCtx make_ctx(uint32_t sb) {
    GemmCtx cx;
    cx.tid = threadIdx.x; cx.wid = cx.tid >> 5; cx.lane = cx.tid & 31;
    cx.gam = cx.lane >> 2; cx.sig = cx.lane & 3;
    const int matid = cx.lane >> 3, mrow = cx.lane & 7;
    cx.wm = (cx.wid & 3) * 32; cx.wn = (cx.wid >> 2) * 64;
    cx.row0 = blockIdx.y * 128; cx.col0 = blockIdx.x * 128;
    cx.sb = sb;
    cx.offA = (uint32_t)((cx.wm + (matid & 1) * 8 + mrow) * 144 + (matid >> 1) * 16);
    cx.offB = (uint32_t)((cx.wn + (matid >> 1) * 8 + mrow) * 144 + (matid & 1) * 16);
    return cx;
}

// ---------------------------------------------------------------------------
// Fused Q/K/V projection GEMM. z=0: Q; z=1: K; z=2: V -> transposed.
// ---------------------------------------------------------------------------
__global__ __launch_bounds__(256)
void gemm_qkv(const fp16* __restrict__ inh, const fp16* __restrict__ wh,
              fp16* __restrict__ qh, fp16* __restrict__ kh, fp16* __restrict__ vth)
{
    extern __shared__ char smem[];
    const int z = blockIdx.z;
    GemmCtx cx = make_ctx(smem_u32(smem));
    float acc[2][8][4];
    gemm_main(inh + (size_t)z * TS, wh + (size_t)z * WS, cx, acc);

    if (z < 2) {
        fp16* dst = (z == 0) ? qh : kh;
#pragma unroll
        for (int mt = 0; mt < 2; mt++)
#pragma unroll
            for (int nt = 0; nt < 8; nt++) {
                int r0 = cx.row0 + cx.wm + mt * 16 + cx.gam;
                int col = cx.col0 + cx.wn + nt * 8 + 2 * cx.sig;
                *(uint32_t*)(dst + (size_t)r0 * NDIM + col) =
                    cvtpack_h(acc[mt][nt][0], acc[mt][nt][1]);
                *(uint32_t*)(dst + (size_t)(r0 + 8) * NDIM + col) =
                    cvtpack_h(acc[mt][nt][2], acc[mt][nt][3]);
            }
    } else {
        fp16* tb = (fp16*)smem;   // [128][130]
        __syncthreads();
#pragma unroll
        for (int mt = 0; mt < 2; mt++)
#pragma unroll
            for (int nt = 0; nt < 8; nt++)
#pragma unroll
                for (int rr = 0; rr < 2; rr++) {
                    int lr = cx.wm + mt * 16 + cx.gam + rr * 8;
                    int lc = cx.wn + nt * 8 + 2 * cx.sig;
                    *(uint32_t*)(tb + lr * 130 + lc) =
                        cvtpack_h(acc[mt][nt][2 * rr], acc[mt][nt][2 * rr + 1]);
                }
        __syncthreads();
#pragma unroll 4
        for (int it = 0; it < 32; it++) {
            int c = (cx.tid >> 6) + it * 4;
            int r = (cx.tid & 63) * 2;
            uint32_t p = pack2_h(tb[r * 130 + c], tb[(r + 1) * 130 + c]);
            *(uint32_t*)(vth + (size_t)(cx.col0 + c) * MROWS + cx.row0 + r) = p;
        }
    }
}

// ---------------------------------------------------------------------------
// Output projection GEMM -> fp32
// ---------------------------------------------------------------------------
__global__ __launch_bounds__(256)
void gemm_out(const fp16* __restrict__ Ah, const fp16* __restrict__ Bh,
              float* __restrict__ Cf)
{
    extern __shared__ char smem[];
    GemmCtx cx = make_ctx(smem_u32(smem));
    float acc[2][8][4];
    gemm_main(Ah, Bh, cx, acc);
#pragma unroll
    for (int mt = 0; mt < 2; mt++)
#pragma unroll
        for (int nt = 0; nt < 8; nt++) {
            int r0 = cx.row0 + cx.wm + mt * 16 + cx.gam;
            int col = cx.col0 + cx.wn + nt * 8 + 2 * cx.sig;
            *(float2*)(Cf + (size_t)r0 * NDIM + col) =
                make_float2(acc[mt][nt][0], acc[mt][nt][1]);
            *(float2*)(Cf + (size_t)(r0 + 8) * NDIM + col) =
                make_float2(acc[mt][nt][2], acc[mt][nt][3]);
        }
}

// ---------------------------------------------------------------------------
// Flash attention (exact R9 version — best measured: 117 us).
// Unshifted softmax P = 2^s (log2e folded into Wq); row sums via all-ones
// MMA; exp of one half overlaps PV MMAs of the other; 4-stage KV pipeline.
// ---------------------------------------------------------------------------
#define QTEN 18432
#define ATEN 9216
#define ASTAGE (2 * ATEN)
#define ASTAGES 4
#define ATT_SMEM (QTEN + ASTAGES * ASTAGE)   /* 92160 */

__global__ __launch_bounds__(256)
void attn_h(const fp16* __restrict__ Qh, const fp16* __restrict__ Kh,
            const fp16* __restrict__ VTh, fp16* __restrict__ Oh)
{
    extern __shared__ char smem[];
    const uint32_t sb = smem_u32(smem);
    const int tid = threadIdx.x, wid = tid >> 5, lane = tid & 31;
    const int gam = lane >> 2, sig = lane & 3;
    const int matid = lane >> 3, mrow = lane & 7;
    const int b = blockIdx.y >> 4, n = blockIdx.y & 15;
    const int f0 = blockIdx.x * 128;
    const size_t qbase = ((size_t)b * SEQ + f0) * DMODEL + n * HDIM;

    const uint32_t offQ = (uint32_t)((wid * 16 + (matid & 1) * 8 + mrow) * 144 + (matid >> 1) * 16);
    const uint32_t offB = (uint32_t)(((matid >> 1) * 8 + mrow) * 144 + (matid & 1) * 16);
    const uint32_t ONES = 0x3C003C00u;   // fp16x2 (1.0, 1.0)

    auto issue_kv = [&](int stage, int t) {
        const int t0 = t * 64;
        const uint32_t s0 = sb + QTEN + stage * ASTAGE;
#pragma unroll
        for (int i = 0; i < 2; i++) {
            int c = tid + 256 * i;
            int r = c >> 3, ch = c & 7;
            uint32_t dst = (uint32_t)(r * 144 + ch * 16);
            size_t krow = ((size_t)b * SEQ + t0 + r) * DMODEL + n * HDIM + ch * 8;
            size_t vrow = ((size_t)(n * HDIM + r)) * MROWS + (size_t)b * SEQ + t0 + ch * 8;
            cp16(s0 + dst,        Kh  + krow);
            cp16(s0 + ATEN + dst, VTh + vrow);
        }
        cp_commit();
    };

    // Q tile, committed with stage 0
#pragma unroll
    for (int i = 0; i < 4; i++) {
        int c = tid + 256 * i;
        int r = c >> 3, ch = c & 7;
        cp16(sb + (uint32_t)(r * 144 + ch * 16), Qh + qbase + (size_t)r * DMODEL + ch * 8);
    }
    issue_kv(0, 0);
    issue_kv(1, 1);
    issue_kv(2, 2);
    issue_kv(3, 3);

    float o[8][4], lacc[4];
#pragma unroll
    for (int nt = 0; nt < 8; nt++)
#pragma unroll
        for (int q = 0; q < 4; q++) o[nt][q] = 0.f;
#pragma unroll
    for (int q = 0; q < 4; q++) lacc[q] = 0.f;

    uint32_t qf[4][4];   // Q fragments, loaded once

    for (int c = 0; c < 32; c++) {
        if (c < 29) cp_wait<3>();
        else if (c == 29) cp_wait<2>();
        else if (c == 30) cp_wait<1>();
        else cp_wait<0>();
        __syncthreads();
        if (c == 0) {
#pragma unroll
            for (int kk = 0; kk < 4; kk++) ldsm4(qf[kk], sb + offQ + kk * 32);
        }
        const uint32_t s0 = sb + QTEN + (c & 3) * ASTAGE;
        const uint32_t kah = s0 + offB, vah = s0 + ATEN + offB;

        // ---- S = Q @ K^T, group-wise ----
        float s[8][4];
#pragma unroll
        for (int nt = 0; nt < 8; nt++)
#pragma unroll
            for (int q = 0; q < 4; q++) s[nt][q] = 0.f;

#pragma unroll
        for (int gp = 0; gp < 2; gp++)
#pragma unroll
            for (int kk = 0; kk < 4; kk++) {
                uint32_t b0[4], b1[4];
                ldsm4(b0, kah + (2 * gp)     * 2304 + kk * 32);
                ldsm4(b1, kah + (2 * gp + 1) * 2304 + kk * 32);
                mma_f16(s[4 * gp + 0], qf[kk], b0[0], b0[1]);
                mma_f16(s[4 * gp + 1], qf[kk], b0[2], b0[3]);
                mma_f16(s[4 * gp + 2], qf[kk], b1[0], b1[1]);
                mma_f16(s[4 * gp + 3], qf[kk], b1[2], b1[3]);
            }

        // ---- halves: exp overlaps PV MMAs of the other half ----
#pragma unroll
        for (int h = 0; h < 2; h++) {
#pragma unroll
            for (int nt = 4 * h; nt < 4 * h + 4; nt++) {
                s[nt][0] = ex2f(s[nt][0]);
                s[nt][1] = ex2f(s[nt][1]);
                s[nt][2] = ex2f(s[nt][2]);
                s[nt][3] = ex2f(s[nt][3]);
            }
#pragma unroll
            for (int k2 = 2 * h; k2 < 2 * h + 2; k2++) {
                uint32_t ph[4];
                ph[0] = cvtpack_h(s[2 * k2][0],     s[2 * k2][1]);
                ph[1] = cvtpack_h(s[2 * k2][2],     s[2 * k2][3]);
                ph[2] = cvtpack_h(s[2 * k2 + 1][0], s[2 * k2 + 1][1]);
                ph[3] = cvtpack_h(s[2 * k2 + 1][2], s[2 * k2 + 1][3]);
#pragma unroll
                for (int gp = 0; gp < 2; gp++) {
                    uint32_t b0[4], b1[4];
                    ldsm4(b0, vah + (2 * gp)     * 2304 + k2 * 32);
                    ldsm4(b1, vah + (2 * gp + 1) * 2304 + k2 * 32);
                    mma_f16(o[4 * gp + 0], ph, b0[0], b0[1]);
                    mma_f16(o[4 * gp + 1], ph, b0[2], b0[3]);
                    mma_f16(o[4 * gp + 2], ph, b1[0], b1[1]);
                    mma_f16(o[4 * gp + 3], ph, b1[2], b1[3]);
                }
                mma_f16(lacc, ph, ONES, ONES);   // row sums
            }
        }
        __syncthreads();
        if (c + 4 < 32) issue_kv(c & 3, c + 4);
    }

    // ---- normalize, store ----
    const float inv0 = 1.f / lacc[0], inv1 = 1.f / lacc[2];
    const size_t ro0 = ((size_t)b * SEQ + f0 + wid * 16 + gam) * DMODEL + n * HDIM;
    const size_t ro1 = ro0 + 8 * DMODEL;
#pragma unroll
    for (int nt = 0; nt < 8; nt++) {
        const int col = nt * 8 + 2 * sig;
        *(uint32_t*)(Oh + ro0 + col) = cvtpack_h(o[nt][0] * inv0, o[nt][1] * inv0);
        *(uint32_t*)(Oh + ro1 + col) = cvtpack_h(o[nt][2] * inv1, o[nt][3] * inv1);
    }
}

// ---------------------------------------------------------------------------
// Launch: cvt(0), tsplit(1), gemm_qkv(2), attn(3), gemm_out(4)
// ---------------------------------------------------------------------------
extern "C" void kernel_launch(void* const* d_in, const int* in_sizes, int n_in,
                              void* d_out, int out_size)
{
    (void)in_sizes; (void)n_in; (void)out_size;
    const float* qin = (const float*)d_in[0];
    const float* kin = (const float*)d_in[1];
    const float* vin = (const float*)d_in[2];
    const float* Wq  = (const float*)d_in[3];
    const float* Wk  = (const float*)d_in[4];
    const float* Wv  = (const float*)d_in[5];
    const float* Wo  = (const float*)d_in[6];
    float* out = (float*)d_out;

    fp16 *inh, *wh, *qh, *kh, *vth, *ah;
    cudaGetSymbolAddress((void**)&inh, g_inh);
    cudaGetSymbolAddress((void**)&wh,  g_wh);
    cudaGetSymbolAddress((void**)&qh,  g_qh);
    cudaGetSymbolAddress((void**)&kh,  g_kh);
    cudaGetSymbolAddress((void**)&vth, g_vth);
    cudaGetSymbolAddress((void**)&ah,  g_ah);

    cudaFuncSetAttribute(gemm_qkv, cudaFuncAttributeMaxDynamicSharedMemorySize, GEMM_SMEM);
    cudaFuncSetAttribute(gemm_out, cudaFuncAttributeMaxDynamicSharedMemorySize, GEMM_SMEM);
    cudaFuncSetAttribute(attn_h,   cudaFuncAttributeMaxDynamicSharedMemorySize, ATT_SMEM);

    cvt_in<<<dim3((unsigned)(TS / 1024), 1, 3), 256>>>(qin, kin, vin, inh);
    tsplit_w<<<dim3(32, 32, 4), dim3(32, 8)>>>(Wq, Wk, Wv, Wo, wh);

    gemm_qkv<<<dim3(NDIM / 128, MROWS / 128, 3), 256, GEMM_SMEM>>>(
        inh, wh, qh, kh, vth);

    attn_h<<<dim3(SEQ / 128, BATCH * NHEADS), 256, ATT_SMEM>>>(
        qh, kh, vth, ah);

    gemm_out<<<dim3(NDIM / 128, MROWS / 128), 256, GEMM_SMEM>>>(
        ah, wh + 3 * WS, out);
}